// round 16
// baseline (speedup 1.0000x reference)
#include <cuda_runtime.h>
#include <cuda_bf16.h>
#include <math.h>
#include <stdint.h>

#define NB 32      // batch
#define NS 256     // seq len
#define NT 36      // NU*ML steps
#define NH 768     // hidden
#define NV 30522   // vocab
#define NVP 30592  // padded vocab = 239*128
#define NG 2304    // 3*NH
#define NML 9
#define NKC 12     // split-k chunks for gh GEMM (768/64)
#define NM 1152    // NT*NB rows of the batched vocab GEMM

// ---------------- static device scratch ----------------
__device__ float g_WS[NM*NH];
__device__ float g_GI[(size_t)NM*NG];
__device__ float g_PGW[NM];
__device__ float g_H[2][NB*NH];
__device__ float g_GHP[NKC*3*NB*NH];
__device__ float g_HALL[(size_t)NM*NH];        // all h_t (fp32)
__device__ float g_CTX[(size_t)NM*NH];         // unnormalized context
__device__ float g_ATTN_ALL[(size_t)NM*NS];    // UNNORMALIZED exp(dot)
__device__ float g_ASUM[NM];                   // sum of exp(dot)
__device__ float g_PGEN_ALL[NM];
__device__ float g_SSC[NM];                    // (1-pgen)/asum
__device__ float g_RS[NM];
__device__ __nv_bfloat16 g_AH_HI[NM*NH];
__device__ __nv_bfloat16 g_AH_LO[NM*NH];
__device__ __nv_bfloat16 g_WS_HI[NM*NH];
__device__ __nv_bfloat16 g_WS_LO[NM*NH];
__device__ __nv_bfloat16 g_WIH_HI[(size_t)NG*NH];
__device__ __nv_bfloat16 g_WIH_LO[(size_t)NG*NH];
__device__ __nv_bfloat16 g_EB_HI[(size_t)NVP*NH];
__device__ __nv_bfloat16 g_EB_LO[(size_t)NVP*NH];

__device__ __forceinline__ float sigf(float v) { return 1.f/(1.f+__expf(-v)); }

__device__ __forceinline__ uint32_t smem_u32(const void* p) {
    uint32_t a;
    asm("{ .reg .u64 t; cvta.to.shared.u64 t, %1; cvt.u32.u64 %0, t; }" : "=r"(a) : "l"(p));
    return a;
}

#define CP_ASYNC16(dst, src) \
    asm volatile("cp.async.cg.shared.global [%0], [%1], 16;" :: "r"(dst), "l"(src) : "memory")
#define CP_COMMIT() asm volatile("cp.async.commit_group;" ::: "memory")
#define CP_WAIT1()  asm volatile("cp.async.wait_group 1;" ::: "memory")
#define CP_WAIT0()  asm volatile("cp.async.wait_group 0;" ::: "memory")

#define LDM4(r, addr) \
    asm volatile("ldmatrix.sync.aligned.m8n8.x4.shared.b16 {%0,%1,%2,%3}, [%4];" \
        : "=r"((r)[0]), "=r"((r)[1]), "=r"((r)[2]), "=r"((r)[3]) : "r"(addr))

#define MMA_BF16(d, a, b0v, b1v) \
    asm volatile("mma.sync.aligned.m16n8k16.row.col.f32.bf16.bf16.f32 " \
        "{%0,%1,%2,%3}, {%4,%5,%6,%7}, {%8,%9}, {%0,%1,%2,%3};" \
        : "+f"((d)[0]), "+f"((d)[1]), "+f"((d)[2]), "+f"((d)[3]) \
        : "r"((a)[0]), "r"((a)[1]), "r"((a)[2]), "r"((a)[3]), "r"(b0v), "r"(b1v))

// ---------------------------------------------------------------------------
__global__ void k_zero() {
    int i = blockIdx.x*256 + threadIdx.x;
    if (i < NM) { g_RS[i] = 0.f; g_ASUM[i] = 0.f; }
}

// P0: build WS[t][b][:] (fp32 + bf16 hi/lo)
__global__ void k_build_ws(const float* __restrict__ dec,
                           const int*   __restrict__ teacher,
                           const float* __restrict__ embed) {
    int t = blockIdx.x, b = blockIdx.y;
    int u = t / NML, m = t % NML;
    const float4* src;
    if (m == 0) {
        src = (const float4*)(dec + ((size_t)b*4 + u)*NH);
    } else {
        int tok = teacher[(b*4 + u)*NML + (m-1)];
        src = (const float4*)(embed + (size_t)tok*NH);
    }
    size_t base = ((size_t)t*NB + b)*NH + (size_t)threadIdx.x*4;
    float4 v = src[threadIdx.x];           // blockDim = 192
    *(float4*)(g_WS + base) = v;
    __nv_bfloat16 h0=__float2bfloat16(v.x), h1=__float2bfloat16(v.y);
    __nv_bfloat16 h2=__float2bfloat16(v.z), h3=__float2bfloat16(v.w);
    g_WS_HI[base]=h0; g_WS_HI[base+1]=h1; g_WS_HI[base+2]=h2; g_WS_HI[base+3]=h3;
    g_WS_LO[base]  =__float2bfloat16(v.x-__bfloat162float(h0));
    g_WS_LO[base+1]=__float2bfloat16(v.y-__bfloat162float(h1));
    g_WS_LO[base+2]=__float2bfloat16(v.z-__bfloat162float(h2));
    g_WS_LO[base+3]=__float2bfloat16(v.w-__bfloat162float(h3));
}

__global__ void k_copy_h(const float* __restrict__ hid) {
    int i = blockIdx.x*blockDim.x + threadIdx.x;
    if (i < NB*NH) g_H[0][i] = hid[i];
}

__global__ void k_pgw(const float* __restrict__ wgen) {
    int r = blockIdx.x*8 + (threadIdx.x >> 5);
    int lane = threadIdx.x & 31;
    const float* wsr = g_WS + (size_t)r*NH;
    float acc = 0.f;
    #pragma unroll
    for (int i = 0; i < 24; i++) acc += wsr[lane + 32*i] * wgen[lane + 32*i];
    #pragma unroll
    for (int off = 16; off; off >>= 1) acc += __shfl_xor_sync(0xffffffffu, acc, off);
    if (lane == 0) g_PGW[r] = acc;
}

// embed -> bf16 hi/lo, padded to NVP rows (pad rows = 0)
__global__ void k_conv_embed(const float* __restrict__ embed) {
    size_t base = ((size_t)blockIdx.x*256 + threadIdx.x) * 4;
    int v = (int)(base / NH);
    float4 val = make_float4(0.f, 0.f, 0.f, 0.f);
    if (v < NV) val = *(const float4*)(embed + base);
    __nv_bfloat16 h0=__float2bfloat16(val.x), h1=__float2bfloat16(val.y);
    __nv_bfloat16 h2=__float2bfloat16(val.z), h3=__float2bfloat16(val.w);
    g_EB_HI[base]=h0; g_EB_HI[base+1]=h1; g_EB_HI[base+2]=h2; g_EB_HI[base+3]=h3;
    g_EB_LO[base]  =__float2bfloat16(val.x-__bfloat162float(h0));
    g_EB_LO[base+1]=__float2bfloat16(val.y-__bfloat162float(h1));
    g_EB_LO[base+2]=__float2bfloat16(val.z-__bfloat162float(h2));
    g_EB_LO[base+3]=__float2bfloat16(val.w-__bfloat162float(h3));
}

// wih -> bf16 hi/lo
__global__ void k_conv_wih(const float* __restrict__ wih) {
    size_t base = ((size_t)blockIdx.x*256 + threadIdx.x) * 4;   // < NG*NH
    float4 val = *(const float4*)(wih + base);
    __nv_bfloat16 h0=__float2bfloat16(val.x), h1=__float2bfloat16(val.y);
    __nv_bfloat16 h2=__float2bfloat16(val.z), h3=__float2bfloat16(val.w);
    g_WIH_HI[base]=h0; g_WIH_HI[base+1]=h1; g_WIH_HI[base+2]=h2; g_WIH_HI[base+3]=h3;
    g_WIH_LO[base]  =__float2bfloat16(val.x-__bfloat162float(h0));
    g_WIH_LO[base+1]=__float2bfloat16(val.y-__bfloat162float(h1));
    g_WIH_LO[base+2]=__float2bfloat16(val.z-__bfloat162float(h2));
    g_WIH_LO[base+3]=__float2bfloat16(val.w-__bfloat162float(h3));
}

// ---------------------------------------------------------------------------
// Shared bf16 hi/lo MMA tile kernel bodies (128x128 tile, 8 warps)
#define BUF_STRIDE  65536
#define VSMEM (2*BUF_STRIDE + 1024)

// GI = WS @ Wih^T + bih   grid (9 m-tiles, 18 n-tiles)
__global__ void __launch_bounds__(256) k_gi_mma(const float* __restrict__ bih) {
    extern __shared__ __align__(16) char smraw[];
    uint32_t sb_raw = smem_u32(smraw);
    uint32_t sb = (sb_raw + 1023u) & ~1023u;
    int tid = threadIdx.x;
    int wid = tid >> 5, lid = tid & 31;
    int warp_m = wid >> 2, warp_n = wid & 3;
    int m0 = blockIdx.x * 128;
    int n0 = blockIdx.y * 128;

    const __nv_bfloat16* gAh = g_WS_HI + (size_t)m0*NH;
    const __nv_bfloat16* gAl = g_WS_LO + (size_t)m0*NH;
    const __nv_bfloat16* gBh = g_WIH_HI + (size_t)n0*NH;
    const __nv_bfloat16* gBl = g_WIH_LO + (size_t)n0*NH;

    float acc[4][4][4];
    #pragma unroll
    for (int i=0;i<4;i++)
        #pragma unroll
        for (int j=0;j<4;j++){acc[i][j][0]=0;acc[i][j][1]=0;acc[i][j][2]=0;acc[i][j][3]=0;}

    auto load_chunk = [&](int kc, int bsel) {
        int kb = kc * 64;
        uint32_t base = sb + bsel*BUF_STRIDE;
        #pragma unroll
        for (int ii = 0; ii < 4; ii++) {
            int i = tid + ii*256;
            int r = i >> 3, f = i & 7;
            uint32_t off = (uint32_t)(r*128 + f*16);
            uint32_t swo = off ^ ((uint32_t)(r & 7) << 4);
            size_t gofs = (size_t)r*NH + kb + f*8;
            CP_ASYNC16(base + swo,         gAh + gofs);
            CP_ASYNC16(base + 16384 + swo, gAl + gofs);
            CP_ASYNC16(base + 32768 + swo, gBh + gofs);
            CP_ASYNC16(base + 49152 + swo, gBl + gofs);
        }
        CP_COMMIT();
    };
    load_chunk(0, 0);

    int lr = lid & 7, lg = lid >> 3;
    for (int kc = 0; kc < 12; kc++) {
        if (kc + 1 < 12) { load_chunk(kc+1, (kc+1)&1); CP_WAIT1(); }
        else             { CP_WAIT0(); }
        __syncthreads();
        uint32_t base = sb + (kc&1)*BUF_STRIDE;
        #pragma unroll
        for (int ks = 0; ks < 4; ks++) {
            uint32_t ah[4][4], al[4][4];
            int cI = ks*2 + (lg >> 1);
            #pragma unroll
            for (int mi = 0; mi < 4; mi++) {
                int row = warp_m*64 + mi*16 + (lg & 1)*8 + lr;
                uint32_t addr = base + (uint32_t)(row*128) + ((uint32_t)(cI ^ (row & 7)) << 4);
                LDM4(ah[mi], addr);
                LDM4(al[mi], addr + 16384);
            }
            uint32_t bh[2][4], bl[2][4];
            #pragma unroll
            for (int np = 0; np < 2; np++) {
                int row = warp_n*32 + np*16 + (lg & 1)*8 + lr;
                uint32_t addr = base + 32768 + (uint32_t)(row*128) + ((uint32_t)(cI ^ (row & 7)) << 4);
                LDM4(bh[np], addr);
                LDM4(bl[np], addr + 16384);
            }
            #pragma unroll
            for (int mi = 0; mi < 4; mi++)
                #pragma unroll
                for (int np = 0; np < 2; np++)
                    #pragma unroll
                    for (int sub = 0; sub < 2; sub++) {
                        float* d = acc[mi][np*2 + sub];
                        MMA_BF16(d, ah[mi], bh[np][sub], bh[np][sub+2]);
                        MMA_BF16(d, ah[mi], bl[np][sub], bl[np][sub+2]);
                        MMA_BF16(d, al[mi], bh[np][sub], bh[np][sub+2]);
                    }
        }
        __syncthreads();
    }

    int g = lid >> 2, q = lid & 3;
    #pragma unroll
    for (int mi = 0; mi < 4; mi++)
        #pragma unroll
        for (int h = 0; h < 2; h++) {
            int m = m0 + warp_m*64 + mi*16 + h*8 + g;
            #pragma unroll
            for (int nj = 0; nj < 4; nj++) {
                int n = n0 + warp_n*32 + nj*8 + q*2;
                float2 o = make_float2(acc[mi][nj][h*2+0] + bih[n],
                                       acc[mi][nj][h*2+1] + bih[n+1]);
                *(float2*)(g_GI + (size_t)m*NG + n) = o;
            }
        }
}

// ---------------------------------------------------------------------------
// K1: split-K partials of gh = h @ Whh^T  (unchanged)
__global__ void __launch_bounds__(256) k_gru_partial(const float* __restrict__ whh, int hb) {
    __shared__ __align__(16) float Hs[64][36];
    __shared__ float Ws[3][64][33];
    const float* hold = g_H[hb];
    int tx = threadIdx.x, ty = threadIdx.y;
    int tid = ty*32 + tx;
    int j0 = blockIdx.x * 32;
    int kc = blockIdx.y * 64;
    for (int i = tid; i < 2048; i += 256) {
        int bb = i >> 6, kk = i & 63;
        Hs[kk][bb] = hold[bb*NH + kc + kk];
    }
    for (int i = tid; i < 96*16; i += 256) {
        int r = i >> 4, f = i & 15;
        int g = r >> 5, j = r & 31;
        float4 v = *(const float4*)(whh + (size_t)(g*NH + j0 + j)*NH + kc + f*4);
        int kk = f*4;
        Ws[g][kk][j]=v.x; Ws[g][kk+1][j]=v.y; Ws[g][kk+2][j]=v.z; Ws[g][kk+3][j]=v.w;
    }
    __syncthreads();
    float ar[4]={0,0,0,0}, az[4]={0,0,0,0}, an[4]={0,0,0,0};
    #pragma unroll
    for (int k = 0; k < 64; k++) {
        float4 h4 = *(const float4*)&Hs[k][ty*4];
        float wr = Ws[0][k][tx], wz = Ws[1][k][tx], wn = Ws[2][k][tx];
        ar[0]+=h4.x*wr; ar[1]+=h4.y*wr; ar[2]+=h4.z*wr; ar[3]+=h4.w*wr;
        az[0]+=h4.x*wz; az[1]+=h4.y*wz; az[2]+=h4.z*wz; az[3]+=h4.w*wz;
        an[0]+=h4.x*wn; an[1]+=h4.y*wn; an[2]+=h4.z*wn; an[3]+=h4.w*wn;
    }
    int j = j0 + tx;
    int kcid = blockIdx.y;
    #pragma unroll
    for (int i = 0; i < 4; i++) {
        int b = ty*4 + i;
        g_GHP[(((size_t)kcid*3 + 0)*NB + b)*NH + j] = ar[i];
        g_GHP[(((size_t)kcid*3 + 1)*NB + b)*NH + j] = az[i];
        g_GHP[(((size_t)kcid*3 + 2)*NB + b)*NH + j] = an[i];
    }
}

// K1b: combine -> h_new (+ fp32 HALL + bf16 hi/lo rows)
__global__ void k_gru_combine(const float* __restrict__ bhh, int t, int hb) {
    const float* hold = g_H[hb];
    float* hnew = g_H[hb^1];
    int gid = blockIdx.x*256 + threadIdx.x;   // < 24576
    int b = gid / NH, j = gid - b*NH;
    float gr = bhh[j], gz = bhh[NH + j], gn = bhh[2*NH + j];
    #pragma unroll
    for (int kc = 0; kc < NKC; kc++) {
        gr += g_GHP[(((size_t)kc*3 + 0)*NB + b)*NH + j];
        gz += g_GHP[(((size_t)kc*3 + 1)*NB + b)*NH + j];
        gn += g_GHP[(((size_t)kc*3 + 2)*NB + b)*NH + j];
    }
    const float* gi = g_GI + ((size_t)t*NB + b)*NG;
    float r = sigf(gi[j] + gr);
    float z = sigf(gi[NH + j] + gz);
    float n = tanhf(gi[2*NH + j] + r*gn);
    float hp = hold[b*NH + j];
    float hv = (1.f - z)*n + z*hp;
    hnew[b*NH + j] = hv;
    size_t arow = ((size_t)t*NB + b)*NH + j;
    g_HALL[arow] = hv;
    __nv_bfloat16 hi = __float2bfloat16(hv);
    g_AH_HI[arow] = hi;
    g_AH_LO[arow] = __float2bfloat16(hv - __bfloat162float(hi));
}

// ---------------------------------------------------------------------------
// Batched attention dots: grid (4 s-tiles, 32 b). e = exp(enc.h), masked -> 0.
__global__ void __launch_bounds__(256) k_attn_dots(const float* __restrict__ enc,
                                                   const int*   __restrict__ x) {
    __shared__ float Hs2[64*37];
    __shared__ float Es2[64*65];
    int st = blockIdx.x, b = blockIdx.y;
    int tid = threadIdx.x;
    int s = tid & 63, tg = tid >> 6;     // tg in 0..3 -> 9 t's each
    int sg = st*64 + s;
    float acc[9];
    #pragma unroll
    for (int i=0;i<9;i++) acc[i]=0.f;
    for (int kc = 0; kc < 12; kc++) {
        int kb = kc*64;
        for (int idx = tid; idx < 576; idx += 256) {
            int t = idx >> 4, kq = idx & 15;
            float4 v = *(const float4*)(g_HALL + ((size_t)(t*NB+b))*NH + kb + kq*4);
            int k4 = kq*4;
            Hs2[(k4+0)*37 + t]=v.x; Hs2[(k4+1)*37 + t]=v.y;
            Hs2[(k4+2)*37 + t]=v.z; Hs2[(k4+3)*37 + t]=v.w;
        }
        for (int idx = tid; idx < 1024; idx += 256) {
            int ss = idx >> 4, kq = idx & 15;
            float4 v = *(const float4*)(enc + ((size_t)b*NS + st*64 + ss)*NH + kb + kq*4);
            int k4 = kq*4;
            Es2[(k4+0)*65 + ss]=v.x; Es2[(k4+1)*65 + ss]=v.y;
            Es2[(k4+2)*65 + ss]=v.z; Es2[(k4+3)*65 + ss]=v.w;
        }
        __syncthreads();
        #pragma unroll 4
        for (int kk = 0; kk < 64; kk++) {
            float ev = Es2[kk*65 + s];
            #pragma unroll
            for (int i = 0; i < 9; i++)
                acc[i] += Hs2[kk*37 + tg*9 + i] * ev;
        }
        __syncthreads();
    }
    int masked = (x[b*NS + sg] == 0);
    #pragma unroll
    for (int i = 0; i < 9; i++) {
        int t = tg*9 + i;
        float e = masked ? 0.f : __expf(acc[i]);   // |acc| <= ~15, no max needed
        g_ATTN_ALL[((size_t)(t*NB+b))*NS + sg] = e;
        Es2[t*65 + s] = e;                          // reuse smem as ae[36][65]
    }
    __syncthreads();
    if (tid < 36) {
        float sum = 0.f;
        #pragma unroll 8
        for (int i = 0; i < 64; i++) sum += Es2[tid*65 + i];
        atomicAdd(&g_ASUM[tid*NB + b], sum);
    }
}

// Batched context (unnormalized): grid (6 h-tiles, 32 b)
__global__ void __launch_bounds__(256) k_ctx(const float* __restrict__ enc) {
    __shared__ float As2[64*40];
    __shared__ float Es3[64*132];
    int h0 = blockIdx.x * 128, b = blockIdx.y;
    int tid = threadIdx.x;
    int h = tid & 127, tg = tid >> 7;    // tg in 0..1 -> 18 t's each
    float acc[18];
    #pragma unroll
    for (int i=0;i<18;i++) acc[i]=0.f;
    for (int sc = 0; sc < 4; sc++) {
        int sb = sc*64;
        for (int idx = tid; idx < 576; idx += 256) {
            int t = idx >> 4, sq = idx & 15;
            float4 v = *(const float4*)(g_ATTN_ALL + ((size_t)(t*NB+b))*NS + sb + sq*4);
            int s4 = sq*4;
            As2[(s4+0)*40 + t]=v.x; As2[(s4+1)*40 + t]=v.y;
            As2[(s4+2)*40 + t]=v.z; As2[(s4+3)*40 + t]=v.w;
        }
        for (int idx = tid; idx < 2048; idx += 256) {
            int ss = idx >> 5, hq = idx & 31;
            float4 v = *(const float4*)(enc + ((size_t)b*NS + sb + ss)*NH + h0 + hq*4);
            *(float4*)&Es3[ss*132 + hq*4] = v;
        }
        __syncthreads();
        #pragma unroll 4
        for (int kk = 0; kk < 64; kk++) {
            float ev = Es3[kk*132 + h];
            #pragma unroll
            for (int i = 0; i < 18; i++)
                acc[i] += As2[kk*40 + tg + 2*i] * ev;
        }
        __syncthreads();
    }
    #pragma unroll
    for (int i = 0; i < 18; i++) {
        int t = tg + 2*i;
        g_CTX[((size_t)(t*NB+b))*NH + h0 + h] = acc[i];
    }
}

// p_gen + scatter scale: grid 36 blocks x 256
__global__ void k_pgen(const float* __restrict__ wgen, const float* __restrict__ wgenb) {
    int t = blockIdx.x;
    int w = threadIdx.x >> 5, lane = threadIdx.x & 31;
    int bb = w*4;
    for (int k = 0; k < 4; k++, bb = w*4 + k) {
        if (bb >= NB) break;
        int m = t*NB + bb;
        float a1 = 0.f, a2 = 0.f;
        #pragma unroll
        for (int i = 0; i < 24; i++) {
            int kk = lane + 32*i;
            a1 += g_HALL[(size_t)m*NH + kk] * wgen[NH + kk];
            a2 += g_CTX [(size_t)m*NH + kk] * wgen[2*NH + kk];
        }
        #pragma unroll
        for (int off = 16; off; off >>= 1) {
            a1 += __shfl_xor_sync(0xffffffffu, a1, off);
            a2 += __shfl_xor_sync(0xffffffffu, a2, off);
        }
        if (lane == 0) {
            float asum = g_ASUM[m];
            float pg = sigf(g_PGW[m] + a1 + a2/asum + wgenb[0]);
            g_PGEN_ALL[m] = pg;
            g_SSC[m] = (1.f - pg) / asum;
        }
    }
}

// ---------------------------------------------------------------------------
// K3: batched vocab GEMM via mma.sync bf16 (hi/lo split), fused exp + rowsum.
__global__ void __launch_bounds__(256) k_vocab_mma(float* __restrict__ out) {
    extern __shared__ __align__(16) char smraw[];
    uint32_t sb_raw = smem_u32(smraw);
    uint32_t sb = (sb_raw + 1023u) & ~1023u;
    char* smp = smraw + (sb - sb_raw);

    int tid = threadIdx.x;
    int wid = tid >> 5, lid = tid & 31;
    int warp_m = wid >> 2, warp_n = wid & 3;
    int m0 = blockIdx.x * 128;
    int n0 = blockIdx.y * 128;

    const __nv_bfloat16* gAh = g_AH_HI + (size_t)m0*NH;
    const __nv_bfloat16* gAl = g_AH_LO + (size_t)m0*NH;
    const __nv_bfloat16* gBh = g_EB_HI + (size_t)n0*NH;
    const __nv_bfloat16* gBl = g_EB_LO + (size_t)n0*NH;

    float acc[4][4][4];
    #pragma unroll
    for (int i=0;i<4;i++)
        #pragma unroll
        for (int j=0;j<4;j++) { acc[i][j][0]=0;acc[i][j][1]=0;acc[i][j][2]=0;acc[i][j][3]=0; }

    auto load_chunk = [&](int kc, int bsel) {
        int kb = kc * 64;
        uint32_t base = sb + bsel*BUF_STRIDE;
        #pragma unroll
        for (int ii = 0; ii < 4; ii++) {
            int i = tid + ii*256;
            int r = i >> 3, f = i & 7;
            uint32_t off = (uint32_t)(r*128 + f*16);
            uint32_t swo = off ^ ((uint32_t)(r & 7) << 4);
            size_t gofs = (size_t)r*NH + kb + f*8;
            CP_ASYNC16(base + swo,           gAh + gofs);
            CP_ASYNC16(base + 16384 + swo,   gAl + gofs);
            CP_ASYNC16(base + 32768 + swo,   gBh + gofs);
            CP_ASYNC16(base + 49152 + swo,   gBl + gofs);
        }
        CP_COMMIT();
    };

    load_chunk(0, 0);

    int lr = lid & 7, lg = lid >> 3;
    for (int kc = 0; kc < 12; kc++) {
        if (kc + 1 < 12) { load_chunk(kc+1, (kc+1)&1); CP_WAIT1(); }
        else             { CP_WAIT0(); }
        __syncthreads();

        uint32_t base = sb + (kc&1)*BUF_STRIDE;
        #pragma unroll
        for (int ks = 0; ks < 4; ks++) {
            uint32_t ah[4][4], al[4][4];
            int cI = ks*2 + (lg >> 1);
            #pragma unroll
            for (int mi = 0; mi < 4; mi++) {
                int row = warp_m*64 + mi*16 + (lg & 1)*8 + lr;
                uint32_t addr = base + (uint32_t)(row*128) + ((uint32_t)(cI ^ (row & 7)) << 4);
                LDM4(ah[mi], addr);
                LDM4(al[mi], addr + 16384);
            }
            uint32_t bh[2][4], bl[2][4];
            #pragma unroll
            for (int np = 0; np < 2; np++) {
                int row = warp_n*32 + np*16 + (lg & 1)*8 + lr;
                uint32_t addr = base + 32768 + (uint32_t)(row*128) + ((uint32_t)(cI ^ (row & 7)) << 4);
                LDM4(bh[np], addr);
                LDM4(bl[np], addr + 16384);
            }
            #pragma unroll
            for (int mi = 0; mi < 4; mi++) {
                #pragma unroll
                for (int np = 0; np < 2; np++) {
                    #pragma unroll
                    for (int sub = 0; sub < 2; sub++) {
                        float* d = acc[mi][np*2 + sub];
                        MMA_BF16(d, ah[mi], bh[np][sub], bh[np][sub+2]);
                        MMA_BF16(d, ah[mi], bl[np][sub], bl[np][sub+2]);
                        MMA_BF16(d, al[mi], bh[np][sub], bh[np][sub+2]);
                    }
                }
            }
        }
        __syncthreads();
    }

    float* srow = (float*)smp;
    if (tid < 128) srow[tid] = 0.f;
    __syncthreads();

    int g = lid >> 2, q = lid & 3;
    #pragma unroll
    for (int mi = 0; mi < 4; mi++) {
        #pragma unroll
        for (int h = 0; h < 2; h++) {
            int mrow = warp_m*64 + mi*16 + h*8 + g;
            int m = m0 + mrow;
            int tt = m >> 5, bb = m & 31;
            float* orow = out + ((size_t)bb*NT + tt)*NV;
            float rs = 0.f;
            #pragma unroll
            for (int nj = 0; nj < 4; nj++) {
                int v = n0 + warp_n*32 + nj*8 + q*2;
                float e0 = __expf(acc[mi][nj][h*2 + 0]);
                float e1 = __expf(acc[mi][nj][h*2 + 1]);
                if (v + 1 < NV) {
                    *(float2*)(orow + v) = make_float2(e0, e1);
                    rs += e0 + e1;
                } else if (v < NV) {
                    orow[v] = e0;
                    rs += e0;
                }
            }
            rs += __shfl_xor_sync(0xffffffffu, rs, 1);
            rs += __shfl_xor_sync(0xffffffffu, rs, 2);
            if (q == 0) atomicAdd(&srow[mrow], rs);
        }
    }
    __syncthreads();
    if (tid < 128) atomicAdd(&g_RS[m0 + tid], srow[tid]);
}

// K4: scale out rows by p_gen / rowsum
__global__ void k_scale(float* __restrict__ out) {
    int m = blockIdx.y;
    int tt = m >> 5, bb = m & 31;
    float s = g_PGEN_ALL[m] / g_RS[m];
    float* o = out + ((size_t)bb*NT + tt)*NV;
    int v = (blockIdx.x*256 + threadIdx.x) * 2;
    if (v + 1 < NV) {
        float2 p = *(float2*)(o + v);
        p.x *= s; p.y *= s;
        *(float2*)(o + v) = p;
    } else if (v < NV) {
        o[v] *= s;
    }
}

// K5: scatter pointer distribution
__global__ void k_scat(float* __restrict__ out, const int* __restrict__ x) {
    int t = blockIdx.x, b = blockIdx.y;
    int s = threadIdx.x;
    int m = t*NB + b;
    float add = g_SSC[m] * g_ATTN_ALL[(size_t)m*NS + s];
    atomicAdd(out + ((size_t)b*NT + t)*NV + x[b*NS + s], add);
}

// ---------------------------------------------------------------------------
extern "C" void kernel_launch(void* const* d_in, const int* in_sizes, int n_in,
                              void* d_out, int out_size) {
    (void)in_sizes; (void)n_in; (void)out_size;
    const int*   x     = (const int*)  d_in[0];
    const float* dec   = (const float*)d_in[1];
    const float* enc   = (const float*)d_in[2];
    const float* hid   = (const float*)d_in[3];
    const int*   teach = (const int*)  d_in[5];
    const float* embed = (const float*)d_in[6];
    const float* wih   = (const float*)d_in[7];
    const float* whh   = (const float*)d_in[8];
    const float* bih   = (const float*)d_in[9];
    const float* bhh   = (const float*)d_in[10];
    const float* wgen  = (const float*)d_in[11];
    const float* wgenb = (const float*)d_in[12];
    float* out = (float*)d_out;

    cudaFuncSetAttribute(k_vocab_mma, cudaFuncAttributeMaxDynamicSharedMemorySize, VSMEM);
    cudaFuncSetAttribute(k_gi_mma,    cudaFuncAttributeMaxDynamicSharedMemorySize, VSMEM);

    // --- precompute ---
    k_zero<<<5, 256>>>();
    k_build_ws<<<dim3(NT, NB), 192>>>(dec, teach, embed);
    k_copy_h<<<96, 256>>>(hid);
    k_conv_embed<<<22944, 256>>>(embed);
    k_conv_wih<<<1728, 256>>>(wih);
    k_pgw<<<144, 256>>>(wgen);
    k_gi_mma<<<dim3(9, 18), 256, VSMEM>>>(bih);

    // --- sequential scan: GRU only ---
    for (int t = 0; t < NT; t++) {
        int hb = t & 1;
        k_gru_partial<<<dim3(24, NKC), dim3(32, 8)>>>(whh, hb);
        k_gru_combine<<<96, 256>>>(bhh, t, hb);
    }

    // --- batched attention / context / p_gen ---
    k_attn_dots<<<dim3(4, NB), 256>>>(enc, x);
    k_ctx<<<dim3(6, NB), 256>>>(enc);
    k_pgen<<<NT, 256>>>(wgen, wgenb);

    // --- batched vocab head + finalize ---
    k_vocab_mma<<<dim3(9, 239), 256, VSMEM>>>(out);
    k_scale<<<dim3(60, NM), 256>>>(out);
    k_scat<<<dim3(NT, NB), NS>>>(out, x);
}

// round 17
// speedup vs baseline: 1.0102x; 1.0102x over previous
#include <cuda_runtime.h>
#include <cuda_bf16.h>
#include <math.h>
#include <stdint.h>

#define NB 32      // batch
#define NS 256     // seq len
#define NT 36      // NU*ML steps
#define NH 768     // hidden
#define NV 30522   // vocab
#define NVP 30592  // padded vocab = 239*128
#define NG 2304    // 3*NH
#define NML 9
#define NKC 12     // split-k chunks for gh GEMM (768/64)
#define NM 1152    // NT*NB rows of the batched vocab GEMM

// ---------------- static device scratch ----------------
__device__ float g_WS[NM*NH];
__device__ float g_GI[(size_t)NM*NG];
__device__ float g_PGW[NM];
__device__ float g_H[2][NB*NH];
__device__ float g_GHP[NKC*3*NB*NH];
__device__ float g_HALL[(size_t)NM*NH];        // all h_t (fp32)
__device__ float g_CTX[(size_t)NM*NH];         // unnormalized context
__device__ float g_ATTN_ALL[(size_t)NM*NS];    // UNNORMALIZED exp(dot)
__device__ float g_ASUM[NM];                   // sum of exp(dot)
__device__ float g_PGEN_ALL[NM];
__device__ float g_SSC[NM];                    // (1-pgen)/asum
__device__ float g_RS[NM];
__device__ __nv_bfloat16 g_AH_HI[NM*NH];
__device__ __nv_bfloat16 g_AH_LO[NM*NH];
__device__ __nv_bfloat16 g_WS_HI[NM*NH];
__device__ __nv_bfloat16 g_WS_LO[NM*NH];
__device__ __nv_bfloat16 g_WIH_HI[(size_t)NG*NH];
__device__ __nv_bfloat16 g_WIH_LO[(size_t)NG*NH];
__device__ __nv_bfloat16 g_EB_HI[(size_t)NVP*NH];
__device__ __nv_bfloat16 g_EB_LO[(size_t)NVP*NH];

__device__ __forceinline__ float sigf(float v) { return 1.f/(1.f+__expf(-v)); }

__device__ __forceinline__ uint32_t smem_u32(const void* p) {
    uint32_t a;
    asm("{ .reg .u64 t; cvta.to.shared.u64 t, %1; cvt.u32.u64 %0, t; }" : "=r"(a) : "l"(p));
    return a;
}

#define CP_ASYNC16(dst, src) \
    asm volatile("cp.async.cg.shared.global [%0], [%1], 16;" :: "r"(dst), "l"(src) : "memory")
#define CP_COMMIT() asm volatile("cp.async.commit_group;" ::: "memory")
#define CP_WAIT1()  asm volatile("cp.async.wait_group 1;" ::: "memory")
#define CP_WAIT0()  asm volatile("cp.async.wait_group 0;" ::: "memory")

#define LDM4(r, addr) \
    asm volatile("ldmatrix.sync.aligned.m8n8.x4.shared.b16 {%0,%1,%2,%3}, [%4];" \
        : "=r"((r)[0]), "=r"((r)[1]), "=r"((r)[2]), "=r"((r)[3]) : "r"(addr))

#define MMA_BF16(d, a, b0v, b1v) \
    asm volatile("mma.sync.aligned.m16n8k16.row.col.f32.bf16.bf16.f32 " \
        "{%0,%1,%2,%3}, {%4,%5,%6,%7}, {%8,%9}, {%0,%1,%2,%3};" \
        : "+f"((d)[0]), "+f"((d)[1]), "+f"((d)[2]), "+f"((d)[3]) \
        : "r"((a)[0]), "r"((a)[1]), "r"((a)[2]), "r"((a)[3]), "r"(b0v), "r"(b1v))

// ---------------------------------------------------------------------------
__global__ void k_zero() {
    int i = blockIdx.x*256 + threadIdx.x;
    if (i < NM) { g_RS[i] = 0.f; g_ASUM[i] = 0.f; }
}

// P0: build WS[t][b][:] (fp32 + bf16 hi/lo)
__global__ void k_build_ws(const float* __restrict__ dec,
                           const int*   __restrict__ teacher,
                           const float* __restrict__ embed) {
    int t = blockIdx.x, b = blockIdx.y;
    int u = t / NML, m = t % NML;
    const float4* src;
    if (m == 0) {
        src = (const float4*)(dec + ((size_t)b*4 + u)*NH);
    } else {
        int tok = teacher[(b*4 + u)*NML + (m-1)];
        src = (const float4*)(embed + (size_t)tok*NH);
    }
    size_t base = ((size_t)t*NB + b)*NH + (size_t)threadIdx.x*4;
    float4 v = src[threadIdx.x];           // blockDim = 192
    *(float4*)(g_WS + base) = v;
    __nv_bfloat16 h0=__float2bfloat16(v.x), h1=__float2bfloat16(v.y);
    __nv_bfloat16 h2=__float2bfloat16(v.z), h3=__float2bfloat16(v.w);
    g_WS_HI[base]=h0; g_WS_HI[base+1]=h1; g_WS_HI[base+2]=h2; g_WS_HI[base+3]=h3;
    g_WS_LO[base]  =__float2bfloat16(v.x-__bfloat162float(h0));
    g_WS_LO[base+1]=__float2bfloat16(v.y-__bfloat162float(h1));
    g_WS_LO[base+2]=__float2bfloat16(v.z-__bfloat162float(h2));
    g_WS_LO[base+3]=__float2bfloat16(v.w-__bfloat162float(h3));
}

__global__ void k_copy_h(const float* __restrict__ hid) {
    int i = blockIdx.x*blockDim.x + threadIdx.x;
    if (i < NB*NH) g_H[0][i] = hid[i];
}

__global__ void k_pgw(const float* __restrict__ wgen) {
    int r = blockIdx.x*8 + (threadIdx.x >> 5);
    int lane = threadIdx.x & 31;
    const float* wsr = g_WS + (size_t)r*NH;
    float acc = 0.f;
    #pragma unroll
    for (int i = 0; i < 24; i++) acc += wsr[lane + 32*i] * wgen[lane + 32*i];
    #pragma unroll
    for (int off = 16; off; off >>= 1) acc += __shfl_xor_sync(0xffffffffu, acc, off);
    if (lane == 0) g_PGW[r] = acc;
}

// embed -> bf16 hi/lo, padded to NVP rows (pad rows = 0)
__global__ void k_conv_embed(const float* __restrict__ embed) {
    size_t base = ((size_t)blockIdx.x*256 + threadIdx.x) * 4;
    int v = (int)(base / NH);
    float4 val = make_float4(0.f, 0.f, 0.f, 0.f);
    if (v < NV) val = *(const float4*)(embed + base);
    __nv_bfloat16 h0=__float2bfloat16(val.x), h1=__float2bfloat16(val.y);
    __nv_bfloat16 h2=__float2bfloat16(val.z), h3=__float2bfloat16(val.w);
    g_EB_HI[base]=h0; g_EB_HI[base+1]=h1; g_EB_HI[base+2]=h2; g_EB_HI[base+3]=h3;
    g_EB_LO[base]  =__float2bfloat16(val.x-__bfloat162float(h0));
    g_EB_LO[base+1]=__float2bfloat16(val.y-__bfloat162float(h1));
    g_EB_LO[base+2]=__float2bfloat16(val.z-__bfloat162float(h2));
    g_EB_LO[base+3]=__float2bfloat16(val.w-__bfloat162float(h3));
}

// wih -> bf16 hi/lo
__global__ void k_conv_wih(const float* __restrict__ wih) {
    size_t base = ((size_t)blockIdx.x*256 + threadIdx.x) * 4;   // < NG*NH
    float4 val = *(const float4*)(wih + base);
    __nv_bfloat16 h0=__float2bfloat16(val.x), h1=__float2bfloat16(val.y);
    __nv_bfloat16 h2=__float2bfloat16(val.z), h3=__float2bfloat16(val.w);
    g_WIH_HI[base]=h0; g_WIH_HI[base+1]=h1; g_WIH_HI[base+2]=h2; g_WIH_HI[base+3]=h3;
    g_WIH_LO[base]  =__float2bfloat16(val.x-__bfloat162float(h0));
    g_WIH_LO[base+1]=__float2bfloat16(val.y-__bfloat162float(h1));
    g_WIH_LO[base+2]=__float2bfloat16(val.z-__bfloat162float(h2));
    g_WIH_LO[base+3]=__float2bfloat16(val.w-__bfloat162float(h3));
}

// ---------------------------------------------------------------------------
// Shared bf16 hi/lo MMA tile kernel bodies (128x128 tile, 8 warps)
#define BUF_STRIDE  65536
#define VSMEM (2*BUF_STRIDE + 1024)

// GI = WS @ Wih^T + bih   grid (9 m-tiles, 18 n-tiles)
__global__ void __launch_bounds__(256) k_gi_mma(const float* __restrict__ bih) {
    extern __shared__ __align__(16) char smraw[];
    uint32_t sb_raw = smem_u32(smraw);
    uint32_t sb = (sb_raw + 1023u) & ~1023u;
    int tid = threadIdx.x;
    int wid = tid >> 5, lid = tid & 31;
    int warp_m = wid >> 2, warp_n = wid & 3;
    int m0 = blockIdx.x * 128;
    int n0 = blockIdx.y * 128;

    const __nv_bfloat16* gAh = g_WS_HI + (size_t)m0*NH;
    const __nv_bfloat16* gAl = g_WS_LO + (size_t)m0*NH;
    const __nv_bfloat16* gBh = g_WIH_HI + (size_t)n0*NH;
    const __nv_bfloat16* gBl = g_WIH_LO + (size_t)n0*NH;

    float acc[4][4][4];
    #pragma unroll
    for (int i=0;i<4;i++)
        #pragma unroll
        for (int j=0;j<4;j++){acc[i][j][0]=0;acc[i][j][1]=0;acc[i][j][2]=0;acc[i][j][3]=0;}

    auto load_chunk = [&](int kc, int bsel) {
        int kb = kc * 64;
        uint32_t base = sb + bsel*BUF_STRIDE;
        #pragma unroll
        for (int ii = 0; ii < 4; ii++) {
            int i = tid + ii*256;
            int r = i >> 3, f = i & 7;
            uint32_t off = (uint32_t)(r*128 + f*16);
            uint32_t swo = off ^ ((uint32_t)(r & 7) << 4);
            size_t gofs = (size_t)r*NH + kb + f*8;
            CP_ASYNC16(base + swo,         gAh + gofs);
            CP_ASYNC16(base + 16384 + swo, gAl + gofs);
            CP_ASYNC16(base + 32768 + swo, gBh + gofs);
            CP_ASYNC16(base + 49152 + swo, gBl + gofs);
        }
        CP_COMMIT();
    };
    load_chunk(0, 0);

    int lr = lid & 7, lg = lid >> 3;
    for (int kc = 0; kc < 12; kc++) {
        if (kc + 1 < 12) { load_chunk(kc+1, (kc+1)&1); CP_WAIT1(); }
        else             { CP_WAIT0(); }
        __syncthreads();
        uint32_t base = sb + (kc&1)*BUF_STRIDE;
        #pragma unroll
        for (int ks = 0; ks < 4; ks++) {
            uint32_t ah[4][4], al[4][4];
            int cI = ks*2 + (lg >> 1);
            #pragma unroll
            for (int mi = 0; mi < 4; mi++) {
                int row = warp_m*64 + mi*16 + (lg & 1)*8 + lr;
                uint32_t addr = base + (uint32_t)(row*128) + ((uint32_t)(cI ^ (row & 7)) << 4);
                LDM4(ah[mi], addr);
                LDM4(al[mi], addr + 16384);
            }
            uint32_t bh[2][4], bl[2][4];
            #pragma unroll
            for (int np = 0; np < 2; np++) {
                int row = warp_n*32 + np*16 + (lg & 1)*8 + lr;
                uint32_t addr = base + 32768 + (uint32_t)(row*128) + ((uint32_t)(cI ^ (row & 7)) << 4);
                LDM4(bh[np], addr);
                LDM4(bl[np], addr + 16384);
            }
            #pragma unroll
            for (int mi = 0; mi < 4; mi++)
                #pragma unroll
                for (int np = 0; np < 2; np++)
                    #pragma unroll
                    for (int sub = 0; sub < 2; sub++) {
                        float* d = acc[mi][np*2 + sub];
                        MMA_BF16(d, ah[mi], bh[np][sub], bh[np][sub+2]);
                        MMA_BF16(d, ah[mi], bl[np][sub], bl[np][sub+2]);
                        MMA_BF16(d, al[mi], bh[np][sub], bh[np][sub+2]);
                    }
        }
        __syncthreads();
    }

    int g = lid >> 2, q = lid & 3;
    #pragma unroll
    for (int mi = 0; mi < 4; mi++)
        #pragma unroll
        for (int h = 0; h < 2; h++) {
            int m = m0 + warp_m*64 + mi*16 + h*8 + g;
            #pragma unroll
            for (int nj = 0; nj < 4; nj++) {
                int n = n0 + warp_n*32 + nj*8 + q*2;
                float2 o = make_float2(acc[mi][nj][h*2+0] + bih[n],
                                       acc[mi][nj][h*2+1] + bih[n+1]);
                *(float2*)(g_GI + (size_t)m*NG + n) = o;
            }
        }
}

// ---------------------------------------------------------------------------
// K1: split-K partials of gh = h @ Whh^T  (unchanged)
__global__ void __launch_bounds__(256) k_gru_partial(const float* __restrict__ whh, int hb) {
    __shared__ __align__(16) float Hs[64][36];
    __shared__ float Ws[3][64][33];
    const float* hold = g_H[hb];
    int tx = threadIdx.x, ty = threadIdx.y;
    int tid = ty*32 + tx;
    int j0 = blockIdx.x * 32;
    int kc = blockIdx.y * 64;
    for (int i = tid; i < 2048; i += 256) {
        int bb = i >> 6, kk = i & 63;
        Hs[kk][bb] = hold[bb*NH + kc + kk];
    }
    for (int i = tid; i < 96*16; i += 256) {
        int r = i >> 4, f = i & 15;
        int g = r >> 5, j = r & 31;
        float4 v = *(const float4*)(whh + (size_t)(g*NH + j0 + j)*NH + kc + f*4);
        int kk = f*4;
        Ws[g][kk][j]=v.x; Ws[g][kk+1][j]=v.y; Ws[g][kk+2][j]=v.z; Ws[g][kk+3][j]=v.w;
    }
    __syncthreads();
    float ar[4]={0,0,0,0}, az[4]={0,0,0,0}, an[4]={0,0,0,0};
    #pragma unroll
    for (int k = 0; k < 64; k++) {
        float4 h4 = *(const float4*)&Hs[k][ty*4];
        float wr = Ws[0][k][tx], wz = Ws[1][k][tx], wn = Ws[2][k][tx];
        ar[0]+=h4.x*wr; ar[1]+=h4.y*wr; ar[2]+=h4.z*wr; ar[3]+=h4.w*wr;
        az[0]+=h4.x*wz; az[1]+=h4.y*wz; az[2]+=h4.z*wz; az[3]+=h4.w*wz;
        an[0]+=h4.x*wn; an[1]+=h4.y*wn; an[2]+=h4.z*wn; an[3]+=h4.w*wn;
    }
    int j = j0 + tx;
    int kcid = blockIdx.y;
    #pragma unroll
    for (int i = 0; i < 4; i++) {
        int b = ty*4 + i;
        g_GHP[(((size_t)kcid*3 + 0)*NB + b)*NH + j] = ar[i];
        g_GHP[(((size_t)kcid*3 + 1)*NB + b)*NH + j] = az[i];
        g_GHP[(((size_t)kcid*3 + 2)*NB + b)*NH + j] = an[i];
    }
}

// K1b: combine -> h_new (+ fp32 HALL + bf16 hi/lo rows)
__global__ void k_gru_combine(const float* __restrict__ bhh, int t, int hb) {
    const float* hold = g_H[hb];
    float* hnew = g_H[hb^1];
    int gid = blockIdx.x*256 + threadIdx.x;   // < 24576
    int b = gid / NH, j = gid - b*NH;
    float gr = bhh[j], gz = bhh[NH + j], gn = bhh[2*NH + j];
    #pragma unroll
    for (int kc = 0; kc < NKC; kc++) {
        gr += g_GHP[(((size_t)kc*3 + 0)*NB + b)*NH + j];
        gz += g_GHP[(((size_t)kc*3 + 1)*NB + b)*NH + j];
        gn += g_GHP[(((size_t)kc*3 + 2)*NB + b)*NH + j];
    }
    const float* gi = g_GI + ((size_t)t*NB + b)*NG;
    float r = sigf(gi[j] + gr);
    float z = sigf(gi[NH + j] + gz);
    float n = tanhf(gi[2*NH + j] + r*gn);
    float hp = hold[b*NH + j];
    float hv = (1.f - z)*n + z*hp;
    hnew[b*NH + j] = hv;
    size_t arow = ((size_t)t*NB + b)*NH + j;
    g_HALL[arow] = hv;
    __nv_bfloat16 hi = __float2bfloat16(hv);
    g_AH_HI[arow] = hi;
    g_AH_LO[arow] = __float2bfloat16(hv - __bfloat162float(hi));
}

// ---------------------------------------------------------------------------
// Batched attention dots: grid (4 s-tiles, 32 b). e = exp(enc.h), masked -> 0.
__global__ void __launch_bounds__(256) k_attn_dots(const float* __restrict__ enc,
                                                   const int*   __restrict__ x) {
    __shared__ float Hs2[64*37];
    __shared__ float Es2[64*65];
    int st = blockIdx.x, b = blockIdx.y;
    int tid = threadIdx.x;
    int s = tid & 63, tg = tid >> 6;     // tg in 0..3 -> 9 t's each
    int sg = st*64 + s;
    float acc[9];
    #pragma unroll
    for (int i=0;i<9;i++) acc[i]=0.f;
    for (int kc = 0; kc < 12; kc++) {
        int kb = kc*64;
        for (int idx = tid; idx < 576; idx += 256) {
            int t = idx >> 4, kq = idx & 15;
            float4 v = *(const float4*)(g_HALL + ((size_t)(t*NB+b))*NH + kb + kq*4);
            int k4 = kq*4;
            Hs2[(k4+0)*37 + t]=v.x; Hs2[(k4+1)*37 + t]=v.y;
            Hs2[(k4+2)*37 + t]=v.z; Hs2[(k4+3)*37 + t]=v.w;
        }
        for (int idx = tid; idx < 1024; idx += 256) {
            int ss = idx >> 4, kq = idx & 15;
            float4 v = *(const float4*)(enc + ((size_t)b*NS + st*64 + ss)*NH + kb + kq*4);
            int k4 = kq*4;
            Es2[(k4+0)*65 + ss]=v.x; Es2[(k4+1)*65 + ss]=v.y;
            Es2[(k4+2)*65 + ss]=v.z; Es2[(k4+3)*65 + ss]=v.w;
        }
        __syncthreads();
        #pragma unroll 4
        for (int kk = 0; kk < 64; kk++) {
            float ev = Es2[kk*65 + s];
            #pragma unroll
            for (int i = 0; i < 9; i++)
                acc[i] += Hs2[kk*37 + tg*9 + i] * ev;
        }
        __syncthreads();
    }
    int masked = (x[b*NS + sg] == 0);
    #pragma unroll
    for (int i = 0; i < 9; i++) {
        int t = tg*9 + i;
        float e = masked ? 0.f : __expf(acc[i]);   // |acc| <= ~15, no max needed
        g_ATTN_ALL[((size_t)(t*NB+b))*NS + sg] = e;
        Es2[t*65 + s] = e;                          // reuse smem as ae[36][65]
    }
    __syncthreads();
    if (tid < 36) {
        float sum = 0.f;
        #pragma unroll 8
        for (int i = 0; i < 64; i++) sum += Es2[tid*65 + i];
        atomicAdd(&g_ASUM[tid*NB + b], sum);
    }
}

// Batched context (unnormalized): grid (6 h-tiles, 32 b)
__global__ void __launch_bounds__(256) k_ctx(const float* __restrict__ enc) {
    __shared__ float As2[64*40];
    __shared__ float Es3[64*132];
    int h0 = blockIdx.x * 128, b = blockIdx.y;
    int tid = threadIdx.x;
    int h = tid & 127, tg = tid >> 7;    // tg in 0..1 -> 18 t's each
    float acc[18];
    #pragma unroll
    for (int i=0;i<18;i++) acc[i]=0.f;
    for (int sc = 0; sc < 4; sc++) {
        int sb = sc*64;
        for (int idx = tid; idx < 576; idx += 256) {
            int t = idx >> 4, sq = idx & 15;
            float4 v = *(const float4*)(g_ATTN_ALL + ((size_t)(t*NB+b))*NS + sb + sq*4);
            int s4 = sq*4;
            As2[(s4+0)*40 + t]=v.x; As2[(s4+1)*40 + t]=v.y;
            As2[(s4+2)*40 + t]=v.z; As2[(s4+3)*40 + t]=v.w;
        }
        for (int idx = tid; idx < 2048; idx += 256) {
            int ss = idx >> 5, hq = idx & 31;
            float4 v = *(const float4*)(enc + ((size_t)b*NS + sb + ss)*NH + h0 + hq*4);
            *(float4*)&Es3[ss*132 + hq*4] = v;
        }
        __syncthreads();
        #pragma unroll 4
        for (int kk = 0; kk < 64; kk++) {
            float ev = Es3[kk*132 + h];
            #pragma unroll
            for (int i = 0; i < 18; i++)
                acc[i] += As2[kk*40 + tg + 2*i] * ev;
        }
        __syncthreads();
    }
    #pragma unroll
    for (int i = 0; i < 18; i++) {
        int t = tg + 2*i;
        g_CTX[((size_t)(t*NB+b))*NH + h0 + h] = acc[i];
    }
}

// p_gen + scatter scale: grid 36 blocks x 256
__global__ void k_pgen(const float* __restrict__ wgen, const float* __restrict__ wgenb) {
    int t = blockIdx.x;
    int w = threadIdx.x >> 5, lane = threadIdx.x & 31;
    int bb = w*4;
    for (int k = 0; k < 4; k++, bb = w*4 + k) {
        if (bb >= NB) break;
        int m = t*NB + bb;
        float a1 = 0.f, a2 = 0.f;
        #pragma unroll
        for (int i = 0; i < 24; i++) {
            int kk = lane + 32*i;
            a1 += g_HALL[(size_t)m*NH + kk] * wgen[NH + kk];
            a2 += g_CTX [(size_t)m*NH + kk] * wgen[2*NH + kk];
        }
        #pragma unroll
        for (int off = 16; off; off >>= 1) {
            a1 += __shfl_xor_sync(0xffffffffu, a1, off);
            a2 += __shfl_xor_sync(0xffffffffu, a2, off);
        }
        if (lane == 0) {
            float asum = g_ASUM[m];
            float pg = sigf(g_PGW[m] + a1 + a2/asum + wgenb[0]);
            g_PGEN_ALL[m] = pg;
            g_SSC[m] = (1.f - pg) / asum;
        }
    }
}

// ---------------------------------------------------------------------------
// K3: batched vocab GEMM via mma.sync bf16 (hi/lo split), fused exp + rowsum.
__global__ void __launch_bounds__(256) k_vocab_mma(float* __restrict__ out) {
    extern __shared__ __align__(16) char smraw[];
    uint32_t sb_raw = smem_u32(smraw);
    uint32_t sb = (sb_raw + 1023u) & ~1023u;
    char* smp = smraw + (sb - sb_raw);

    int tid = threadIdx.x;
    int wid = tid >> 5, lid = tid & 31;
    int warp_m = wid >> 2, warp_n = wid & 3;
    int m0 = blockIdx.x * 128;
    int n0 = blockIdx.y * 128;

    const __nv_bfloat16* gAh = g_AH_HI + (size_t)m0*NH;
    const __nv_bfloat16* gAl = g_AH_LO + (size_t)m0*NH;
    const __nv_bfloat16* gBh = g_EB_HI + (size_t)n0*NH;
    const __nv_bfloat16* gBl = g_EB_LO + (size_t)n0*NH;

    float acc[4][4][4];
    #pragma unroll
    for (int i=0;i<4;i++)
        #pragma unroll
        for (int j=0;j<4;j++) { acc[i][j][0]=0;acc[i][j][1]=0;acc[i][j][2]=0;acc[i][j][3]=0; }

    auto load_chunk = [&](int kc, int bsel) {
        int kb = kc * 64;
        uint32_t base = sb + bsel*BUF_STRIDE;
        #pragma unroll
        for (int ii = 0; ii < 4; ii++) {
            int i = tid + ii*256;
            int r = i >> 3, f = i & 7;
            uint32_t off = (uint32_t)(r*128 + f*16);
            uint32_t swo = off ^ ((uint32_t)(r & 7) << 4);
            size_t gofs = (size_t)r*NH + kb + f*8;
            CP_ASYNC16(base + swo,           gAh + gofs);
            CP_ASYNC16(base + 16384 + swo,   gAl + gofs);
            CP_ASYNC16(base + 32768 + swo,   gBh + gofs);
            CP_ASYNC16(base + 49152 + swo,   gBl + gofs);
        }
        CP_COMMIT();
    };

    load_chunk(0, 0);

    int lr = lid & 7, lg = lid >> 3;
    for (int kc = 0; kc < 12; kc++) {
        if (kc + 1 < 12) { load_chunk(kc+1, (kc+1)&1); CP_WAIT1(); }
        else             { CP_WAIT0(); }
        __syncthreads();

        uint32_t base = sb + (kc&1)*BUF_STRIDE;
        #pragma unroll
        for (int ks = 0; ks < 4; ks++) {
            uint32_t ah[4][4], al[4][4];
            int cI = ks*2 + (lg >> 1);
            #pragma unroll
            for (int mi = 0; mi < 4; mi++) {
                int row = warp_m*64 + mi*16 + (lg & 1)*8 + lr;
                uint32_t addr = base + (uint32_t)(row*128) + ((uint32_t)(cI ^ (row & 7)) << 4);
                LDM4(ah[mi], addr);
                LDM4(al[mi], addr + 16384);
            }
            uint32_t bh[2][4], bl[2][4];
            #pragma unroll
            for (int np = 0; np < 2; np++) {
                int row = warp_n*32 + np*16 + (lg & 1)*8 + lr;
                uint32_t addr = base + 32768 + (uint32_t)(row*128) + ((uint32_t)(cI ^ (row & 7)) << 4);
                LDM4(bh[np], addr);
                LDM4(bl[np], addr + 16384);
            }
            #pragma unroll
            for (int mi = 0; mi < 4; mi++) {
                #pragma unroll
                for (int np = 0; np < 2; np++) {
                    #pragma unroll
                    for (int sub = 0; sub < 2; sub++) {
                        float* d = acc[mi][np*2 + sub];
                        MMA_BF16(d, ah[mi], bh[np][sub], bh[np][sub+2]);
                        MMA_BF16(d, ah[mi], bl[np][sub], bl[np][sub+2]);
                        MMA_BF16(d, al[mi], bh[np][sub], bh[np][sub+2]);
                    }
                }
            }
        }
        __syncthreads();
    }

    float* srow = (float*)smp;
    if (tid < 128) srow[tid] = 0.f;
    __syncthreads();

    int g = lid >> 2, q = lid & 3;
    #pragma unroll
    for (int mi = 0; mi < 4; mi++) {
        #pragma unroll
        for (int h = 0; h < 2; h++) {
            int mrow = warp_m*64 + mi*16 + h*8 + g;
            int m = m0 + mrow;
            int tt = m >> 5, bb = m & 31;
            float* orow = out + ((size_t)bb*NT + tt)*NV;
            float rs = 0.f;
            #pragma unroll
            for (int nj = 0; nj < 4; nj++) {
                int v = n0 + warp_n*32 + nj*8 + q*2;
                float e0 = __expf(acc[mi][nj][h*2 + 0]);
                float e1 = __expf(acc[mi][nj][h*2 + 1]);
                if (v + 1 < NV) {
                    *(float2*)(orow + v) = make_float2(e0, e1);
                    rs += e0 + e1;
                } else if (v < NV) {
                    orow[v] = e0;
                    rs += e0;
                }
            }
            rs += __shfl_xor_sync(0xffffffffu, rs, 1);
            rs += __shfl_xor_sync(0xffffffffu, rs, 2);
            if (q == 0) atomicAdd(&srow[mrow], rs);
        }
    }
    __syncthreads();
    if (tid < 128) atomicAdd(&g_RS[m0 + tid], srow[tid]);
}

// K4: scale out rows by p_gen / rowsum
__global__ void k_scale(float* __restrict__ out) {
    int m = blockIdx.y;
    int tt = m >> 5, bb = m & 31;
    float s = g_PGEN_ALL[m] / g_RS[m];
    float* o = out + ((size_t)bb*NT + tt)*NV;
    int v = (blockIdx.x*256 + threadIdx.x) * 2;
    if (v + 1 < NV) {
        float2 p = *(float2*)(o + v);
        p.x *= s; p.y *= s;
        *(float2*)(o + v) = p;
    } else if (v < NV) {
        o[v] *= s;
    }
}

// K5: scatter pointer distribution
__global__ void k_scat(float* __restrict__ out, const int* __restrict__ x) {
    int t = blockIdx.x, b = blockIdx.y;
    int s = threadIdx.x;
    int m = t*NB + b;
    float add = g_SSC[m] * g_ATTN_ALL[(size_t)m*NS + s];
    atomicAdd(out + ((size_t)b*NT + t)*NV + x[b*NS + s], add);
}

// ---------------------------------------------------------------------------
extern "C" void kernel_launch(void* const* d_in, const int* in_sizes, int n_in,
                              void* d_out, int out_size) {
    (void)in_sizes; (void)n_in; (void)out_size;
    const int*   x     = (const int*)  d_in[0];
    const float* dec   = (const float*)d_in[1];
    const float* enc   = (const float*)d_in[2];
    const float* hid   = (const float*)d_in[3];
    const int*   teach = (const int*)  d_in[5];
    const float* embed = (const float*)d_in[6];
    const float* wih   = (const float*)d_in[7];
    const float* whh   = (const float*)d_in[8];
    const float* bih   = (const float*)d_in[9];
    const float* bhh   = (const float*)d_in[10];
    const float* wgen  = (const float*)d_in[11];
    const float* wgenb = (const float*)d_in[12];
    float* out = (float*)d_out;

    cudaFuncSetAttribute(k_vocab_mma, cudaFuncAttributeMaxDynamicSharedMemorySize, VSMEM);
    cudaFuncSetAttribute(k_gi_mma,    cudaFuncAttributeMaxDynamicSharedMemorySize, VSMEM);

    // --- precompute ---
    k_zero<<<5, 256>>>();
    k_build_ws<<<dim3(NT, NB), 192>>>(dec, teach, embed);
    k_copy_h<<<96, 256>>>(hid);
    k_conv_embed<<<22944, 256>>>(embed);
    k_conv_wih<<<1728, 256>>>(wih);
    k_pgw<<<144, 256>>>(wgen);
    k_gi_mma<<<dim3(9, 18), 256, VSMEM>>>(bih);

    // --- sequential scan: GRU only ---
    for (int t = 0; t < NT; t++) {
        int hb = t & 1;
        k_gru_partial<<<dim3(24, NKC), dim3(32, 8)>>>(whh, hb);
        k_gru_combine<<<96, 256>>>(bhh, t, hb);
    }

    // --- batched attention / context / p_gen ---
    k_attn_dots<<<dim3(4, NB), 256>>>(enc, x);
    k_ctx<<<dim3(6, NB), 256>>>(enc);
    k_pgen<<<NT, 256>>>(wgen, wgenb);

    // --- batched vocab head + finalize ---
    k_vocab_mma<<<dim3(9, 239), 256, VSMEM>>>(out);
    k_scale<<<dim3(60, NM), 256>>>(out);
    k_scat<<<dim3(NT, NB), NS>>>(out, x);
}